// round 6
// baseline (speedup 1.0000x reference)
#include <cuda_runtime.h>
#include <math.h>

#define BB 256
#define SS 512
#define DD 256
#define HH 256
#define OO 128
#define NCOL 1024            // 4 gates * HH
#define ROWS_PER_CTA 16
#define JS 32                // hidden-j slice per scan CTA
#define CLS 128              // 4 gates * JS
#define NGROUPS 16
#define SCAN_SMEM ((HH*CLS + ROWS_PER_CTA*HH + ROWS_PER_CTA*CLS + ROWS_PER_CTA*JS) * 4)

// ---------- device scratch (static; no runtime allocation) ----------
__device__ float g_XP[(size_t)SS * BB * NCOL];   // [s][b][n], n = gate*256 + j
__device__ float g_H[2][BB * HH];
__device__ unsigned g_barCnt[NGROUPS];
__device__ unsigned g_barGen[NGROUPS];

struct P1Params {
    const float* x;
    const float* Wx[4];
    const float* Wxb[4];
    const float* Whb[4];
    const float* bgate[4];
};
struct ScanParams { const float* Wh[4]; };

// ---------- init: zero state + barriers ----------
__global__ __launch_bounds__(256) void init_kernel() {
    unsigned i = blockIdx.x * blockDim.x + threadIdx.x;
    if (i < 2u * BB * HH) ((float*)g_H)[i] = 0.f;
    if (i < NGROUPS) { g_barCnt[i] = 0u; g_barGen[i] = 0u; }
}

// ---------- phase 1: XP = x @ Wx^T + (Wx_b + Wh_b) + bgate ----------
// M=131072 (m=b*512+s), N=1024, K=256. 64x64 tile, 256 thr, 4x4/thr.
__global__ __launch_bounds__(256) void p1_gemm(P1Params p) {
    __shared__ float As[16][68];
    __shared__ float Bs[16][68];
    const int tid = threadIdx.x;
    const int tm = tid >> 4, tn = tid & 15;
    const int ml = tid >> 2, kl = (tid & 3) * 4;
    const int g  = blockIdx.x >> 2;
    const int j0 = (blockIdx.x << 6) & 255;
    const float* Aptr = p.x + (size_t)(blockIdx.y * 64 + ml) * DD + kl;
    const float* Bptr = p.Wx[g] + (size_t)(j0 + ml) * DD + kl;

    float acc[4][4] = {};
    for (int kt = 0; kt < DD; kt += 16) {
        float4 av = *(const float4*)(Aptr + kt);
        float4 bv = *(const float4*)(Bptr + kt);
        As[kl+0][ml] = av.x; As[kl+1][ml] = av.y; As[kl+2][ml] = av.z; As[kl+3][ml] = av.w;
        Bs[kl+0][ml] = bv.x; Bs[kl+1][ml] = bv.y; Bs[kl+2][ml] = bv.z; Bs[kl+3][ml] = bv.w;
        __syncthreads();
#pragma unroll
        for (int kk = 0; kk < 16; kk++) {
            float4 a = *(const float4*)&As[kk][tm * 4];
            float4 b = *(const float4*)&Bs[kk][tn * 4];
            acc[0][0]=fmaf(a.x,b.x,acc[0][0]); acc[0][1]=fmaf(a.x,b.y,acc[0][1]);
            acc[0][2]=fmaf(a.x,b.z,acc[0][2]); acc[0][3]=fmaf(a.x,b.w,acc[0][3]);
            acc[1][0]=fmaf(a.y,b.x,acc[1][0]); acc[1][1]=fmaf(a.y,b.y,acc[1][1]);
            acc[1][2]=fmaf(a.y,b.z,acc[1][2]); acc[1][3]=fmaf(a.y,b.w,acc[1][3]);
            acc[2][0]=fmaf(a.z,b.x,acc[2][0]); acc[2][1]=fmaf(a.z,b.y,acc[2][1]);
            acc[2][2]=fmaf(a.z,b.z,acc[2][2]); acc[2][3]=fmaf(a.z,b.w,acc[2][3]);
            acc[3][0]=fmaf(a.w,b.x,acc[3][0]); acc[3][1]=fmaf(a.w,b.y,acc[3][1]);
            acc[3][2]=fmaf(a.w,b.z,acc[3][2]); acc[3][3]=fmaf(a.w,b.w,acc[3][3]);
        }
        __syncthreads();
    }

    const int jc = j0 + tn * 4;
    const int n0 = blockIdx.x * 64 + tn * 4;
    float4 wb;
    wb.x = p.Wxb[g][jc+0] + p.Whb[g][jc+0];
    wb.y = p.Wxb[g][jc+1] + p.Whb[g][jc+1];
    wb.z = p.Wxb[g][jc+2] + p.Whb[g][jc+2];
    wb.w = p.Wxb[g][jc+3] + p.Whb[g][jc+3];
#pragma unroll
    for (int rr = 0; rr < 4; rr++) {
        int m = blockIdx.y * 64 + tm * 4 + rr;
        int b = m >> 9;
        int s = m & 511;
        float4 bg4 = *(const float4*)(p.bgate[g] + (size_t)b * HH + jc);
        float4 o;
        o.x = acc[rr][0] + wb.x + bg4.x;
        o.y = acc[rr][1] + wb.y + bg4.y;
        o.z = acc[rr][2] + wb.z + bg4.z;
        o.w = acc[rr][3] + wb.w + bg4.w;
        *(float4*)&g_XP[((size_t)s * BB + b) * NCOL + n0] = o;
    }
}

// ---------- persistent recurrent scan ----------
// 128 CTAs: rb=blockIdx.x>>3 owns batch rows [rb*16,+16); cb=blockIdx.x&7 owns
// j in [cb*32,+32) across 4 gates. Weight slice (128KB) + cell state in SMEM.
__global__ __launch_bounds__(256, 1) void scan_kernel(ScanParams p) {
    extern __shared__ float smem_f[];
    float* Ws  = smem_f;                     // [k][cl] 256*128
    float* hs  = Ws + HH * CLS;              // [r][k]  16*256
    float* pre = hs + ROWS_PER_CTA * HH;     // [r][cl] 16*128
    float* cs  = pre + ROWS_PER_CTA * CLS;   // [r][jj] 16*32

    const int tid = threadIdx.x;
    const int cb = blockIdx.x & 7;
    const int rb = blockIdx.x >> 3;
    const int b0 = rb * ROWS_PER_CTA;
    const int j0 = cb * JS;

    for (int idx = tid; idx < CLS * HH; idx += 256) {
        int cl = idx >> 8;
        int k  = idx & 255;
        int g  = cl >> 5;
        int j  = j0 + (cl & 31);
        Ws[k * CLS + cl] = p.Wh[g][(size_t)j * HH + k];
    }
    for (int idx = tid; idx < ROWS_PER_CTA * JS; idx += 256) cs[idx] = 0.f;
    __syncthreads();

    const int cq = tid & 31;
    const int rp = tid >> 5;
    const int r0 = rp * 2;
    const int c0 = cq * 4;
    const int gg = c0 >> 5;
    const int n0 = gg * 256 + j0 + (c0 & 31);

    for (int t = 0; t < SS; t++) {
        const float* Hin = g_H[t & 1];
        for (int idx = tid * 4; idx < ROWS_PER_CTA * HH; idx += 1024) {
            int r = idx >> 8;
            int k = idx & 255;
            *(float4*)&hs[idx] = *(const float4*)&Hin[(size_t)(b0 + r) * HH + k];
        }
        __syncthreads();

        float a00=0.f,a01=0.f,a02=0.f,a03=0.f,a10=0.f,a11=0.f,a12=0.f,a13=0.f;
        const float* hr0 = hs + r0 * HH;
        const float* hr1 = hr0 + HH;
#pragma unroll 8
        for (int k = 0; k < HH; k++) {
            float4 w = *(const float4*)&Ws[k * CLS + c0];
            float h0 = hr0[k];
            float h1 = hr1[k];
            a00=fmaf(h0,w.x,a00); a01=fmaf(h0,w.y,a01);
            a02=fmaf(h0,w.z,a02); a03=fmaf(h0,w.w,a03);
            a10=fmaf(h1,w.x,a10); a11=fmaf(h1,w.y,a11);
            a12=fmaf(h1,w.z,a12); a13=fmaf(h1,w.w,a13);
        }

        const float* xp = g_XP + ((size_t)t * BB + b0) * NCOL;
        float4 x0 = *(const float4*)&xp[(size_t)r0 * NCOL + n0];
        float4 x1 = *(const float4*)&xp[(size_t)(r0 + 1) * NCOL + n0];
        *(float4*)&pre[r0 * CLS + c0]     = make_float4(a00+x0.x, a01+x0.y, a02+x0.z, a03+x0.w);
        *(float4*)&pre[(r0+1) * CLS + c0] = make_float4(a10+x1.x, a11+x1.y, a12+x1.z, a13+x1.w);
        __syncthreads();

        float* Hout = g_H[(t + 1) & 1];
#pragma unroll
        for (int u = 0; u < 2; u++) {
            int idx = tid * 2 + u;
            int r  = idx >> 5;
            int jj = idx & 31;
            float pg = pre[r * CLS + jj];
            float pi = pre[r * CLS + 32 + jj];
            float pf = pre[r * CLS + 64 + jj];
            float po = pre[r * CLS + 96 + jj];
            float gv = tanhf(pg);
            float iv = 1.f / (1.f + expf(-pi));
            float fv = 1.f / (1.f + expf(-pf));
            float ov = 1.f / (1.f + expf(-po));
            float cv = fmaf(gv, iv, cs[r * JS + jj] * fv);
            cs[r * JS + jj] = cv;
            Hout[(size_t)(b0 + r) * HH + (j0 + jj)] = tanhf(cv) * ov;
        }
        __threadfence();
        __syncthreads();

        if (tid == 0) {
            unsigned arrived = atomicAdd(&g_barCnt[rb], 1u);
            if (arrived == 7u) {
                g_barCnt[rb] = 0u;
                __threadfence();
                atomicExch(&g_barGen[rb], (unsigned)(t + 1));
            } else {
                while (*(volatile unsigned*)&g_barGen[rb] < (unsigned)(t + 1)) { }
            }
            __threadfence();
        }
        __syncthreads();
    }
}

// ---------- final projection + softmax ----------
__global__ __launch_bounds__(128) void proj_softmax(const float* __restrict__ Wph,
                                                    const float* __restrict__ Wphb,
                                                    const float* __restrict__ bp,
                                                    float* __restrict__ out) {
    __shared__ float hsh[HH];
    __shared__ float red[OO];
    const int b = blockIdx.x;
    const int o = threadIdx.x;
    const float* Hfin = g_H[0];           // after t=511, buffer (512 & 1) == 0
    hsh[o]       = Hfin[(size_t)b * HH + o];
    hsh[o + 128] = Hfin[(size_t)b * HH + o + 128];
    __syncthreads();

    float acc = 0.f;
    const float* wr = Wph + (size_t)o * HH;
#pragma unroll 8
    for (int k = 0; k < HH; k += 4) {
        float4 w = *(const float4*)&wr[k];
        acc = fmaf(hsh[k],   w.x, acc);
        acc = fmaf(hsh[k+1], w.y, acc);
        acc = fmaf(hsh[k+2], w.z, acc);
        acc = fmaf(hsh[k+3], w.w, acc);
    }
    float pv = acc + Wphb[o] + bp[(size_t)b * OO + o];

    red[o] = pv;
    __syncthreads();
#pragma unroll
    for (int s = 64; s > 0; s >>= 1) {
        if (o < s) red[o] = fmaxf(red[o], red[o + s]);
        __syncthreads();
    }
    float mx = red[0];
    __syncthreads();
    float e = expf(pv - mx);
    red[o] = e;
    __syncthreads();
#pragma unroll
    for (int s = 64; s > 0; s >>= 1) {
        if (o < s) red[o] += red[o + s];
        __syncthreads();
    }
    out[(size_t)b * OO + o] = e / red[0];
}

// ---------- launch ----------
extern "C" void kernel_launch(void* const* d_in, const int* in_sizes, int n_in,
                              void* d_out, int out_size) {
    (void)in_sizes; (void)n_in; (void)out_size;
    const float* x     = (const float*)d_in[0];
    const float* Wgx_w = (const float*)d_in[1];  const float* Wgx_b = (const float*)d_in[2];
    const float* Wgh_w = (const float*)d_in[3];  const float* Wgh_b = (const float*)d_in[4];
    const float* Wix_w = (const float*)d_in[5];  const float* Wix_b = (const float*)d_in[6];
    const float* Wih_w = (const float*)d_in[7];  const float* Wih_b = (const float*)d_in[8];
    const float* Wfx_w = (const float*)d_in[9];  const float* Wfx_b = (const float*)d_in[10];
    const float* Wfh_w = (const float*)d_in[11]; const float* Wfh_b = (const float*)d_in[12];
    const float* Wox_w = (const float*)d_in[13]; const float* Wox_b = (const float*)d_in[14];
    const float* Woh_w = (const float*)d_in[15]; const float* Woh_b = (const float*)d_in[16];
    const float* Wph_w = (const float*)d_in[17]; const float* Wph_b = (const float*)d_in[18];
    const float* bg    = (const float*)d_in[19];
    const float* bi    = (const float*)d_in[20];
    const float* bf    = (const float*)d_in[21];
    const float* bo    = (const float*)d_in[22];
    const float* bp    = (const float*)d_in[23];
    float* out = (float*)d_out;

    static bool attr_done = false;
    if (!attr_done) {
        cudaFuncSetAttribute(scan_kernel, cudaFuncAttributeMaxDynamicSharedMemorySize, SCAN_SMEM);
        attr_done = true;
    }

    P1Params p1;
    p1.x = x;
    p1.Wx[0] = Wgx_w; p1.Wx[1] = Wix_w; p1.Wx[2] = Wfx_w; p1.Wx[3] = Wox_w;
    p1.Wxb[0] = Wgx_b; p1.Wxb[1] = Wix_b; p1.Wxb[2] = Wfx_b; p1.Wxb[3] = Wox_b;
    p1.Whb[0] = Wgh_b; p1.Whb[1] = Wih_b; p1.Whb[2] = Wfh_b; p1.Whb[3] = Woh_b;
    p1.bgate[0] = bg; p1.bgate[1] = bi; p1.bgate[2] = bf; p1.bgate[3] = bo;

    ScanParams sp;
    sp.Wh[0] = Wgh_w; sp.Wh[1] = Wih_w; sp.Wh[2] = Wfh_w; sp.Wh[3] = Woh_w;

    init_kernel<<<(2 * BB * HH + 255) / 256, 256>>>();
    dim3 g1(NCOL / 64, (BB * SS) / 64);
    p1_gemm<<<g1, 256>>>(p1);
    scan_kernel<<<128, 256, SCAN_SMEM>>>(sp);
    proj_softmax<<<BB, OO>>>(Wph_w, Wph_b, bp, out);
}

// round 7
// speedup vs baseline: 1.6679x; 1.6679x over previous
#include <cuda_runtime.h>
#include <math.h>

#define BB 256
#define SS 512
#define DD 256
#define HH 256
#define OO 128
#define NCOL 1024            // 4 gates * HH
#define ROWS_PER_CTA 16
#define JS 32                // hidden-j slice per scan CTA
#define CLS 128              // 4 gates * JS
#define NGROUPS 16
#define SCAN_SMEM ((HH*CLS + ROWS_PER_CTA*HH + ROWS_PER_CTA*CLS + ROWS_PER_CTA*JS) * 4)

// ---------- device scratch (static; no runtime allocation) ----------
__device__ float g_XP[(size_t)SS * BB * NCOL];   // [s][b][n], n = gate*256 + j
__device__ float g_H[2][BB * HH];
__device__ unsigned g_barCnt[NGROUPS];
__device__ unsigned g_barGen[NGROUPS];

struct P1Params {
    const float* x;
    const float* Wx[4];
    const float* Wxb[4];
    const float* Whb[4];
    const float* bgate[4];
};
struct ScanParams { const float* Wh[4]; };

// ---------- packed f32x2 helpers (Blackwell FFMA2) ----------
__device__ __forceinline__ unsigned long long pack2(float lo, float hi) {
    unsigned long long r;
    asm("mov.b64 %0, {%1, %2};"
        : "=l"(r) : "r"(__float_as_uint(lo)), "r"(__float_as_uint(hi)));
    return r;
}
__device__ __forceinline__ void fma2(unsigned long long& d,
                                     unsigned long long a, unsigned long long b) {
    asm("fma.rn.f32x2 %0, %1, %2, %0;" : "+l"(d) : "l"(a), "l"(b));
}
__device__ __forceinline__ float2 unpack2(unsigned long long v) {
    unsigned lo, hi;
    asm("mov.b64 {%0, %1}, %2;" : "=r"(lo), "=r"(hi) : "l"(v));
    return make_float2(__uint_as_float(lo), __uint_as_float(hi));
}

// ---------- init: zero state + barriers ----------
__global__ __launch_bounds__(256) void init_kernel() {
    unsigned i = blockIdx.x * blockDim.x + threadIdx.x;
    if (i < 2u * BB * HH) ((float*)g_H)[i] = 0.f;
    if (i < NGROUPS) { g_barCnt[i] = 0u; g_barGen[i] = 0u; }
}

// ---------- phase 1: XP = x @ Wx^T + (Wx_b + Wh_b) + bgate ----------
// M=131072 (m=b*512+s), N=1024, K=256. 64x64 tile, 256 thr, 4x4/thr (FFMA2).
__global__ __launch_bounds__(256) void p1_gemm(P1Params p) {
    __shared__ __align__(16) float As[16][68];
    __shared__ __align__(16) float Bs[16][68];
    const int tid = threadIdx.x;
    const int tm = tid >> 4, tn = tid & 15;
    const int ml = tid >> 2, kl = (tid & 3) * 4;
    const int g  = blockIdx.x >> 2;
    const int j0 = (blockIdx.x << 6) & 255;
    const float* Aptr = p.x + (size_t)(blockIdx.y * 64 + ml) * DD + kl;
    const float* Bptr = p.Wx[g] + (size_t)(j0 + ml) * DD + kl;

    unsigned long long acc2[4][2];
#pragma unroll
    for (int r = 0; r < 4; r++) { acc2[r][0] = 0ull; acc2[r][1] = 0ull; }

    for (int kt = 0; kt < DD; kt += 16) {
        float4 av = *(const float4*)(Aptr + kt);
        float4 bv = *(const float4*)(Bptr + kt);
        As[kl+0][ml] = av.x; As[kl+1][ml] = av.y; As[kl+2][ml] = av.z; As[kl+3][ml] = av.w;
        Bs[kl+0][ml] = bv.x; Bs[kl+1][ml] = bv.y; Bs[kl+2][ml] = bv.z; Bs[kl+3][ml] = bv.w;
        __syncthreads();
#pragma unroll
        for (int kk = 0; kk < 16; kk++) {
            float4 a = *(const float4*)&As[kk][tm * 4];
            ulonglong2 b2 = *(const ulonglong2*)&Bs[kk][tn * 4];
            unsigned long long a0 = pack2(a.x, a.x);
            unsigned long long a1 = pack2(a.y, a.y);
            unsigned long long a2 = pack2(a.z, a.z);
            unsigned long long a3 = pack2(a.w, a.w);
            fma2(acc2[0][0], a0, b2.x); fma2(acc2[0][1], a0, b2.y);
            fma2(acc2[1][0], a1, b2.x); fma2(acc2[1][1], a1, b2.y);
            fma2(acc2[2][0], a2, b2.x); fma2(acc2[2][1], a2, b2.y);
            fma2(acc2[3][0], a3, b2.x); fma2(acc2[3][1], a3, b2.y);
        }
        __syncthreads();
    }

    const int jc = j0 + tn * 4;
    const int n0 = blockIdx.x * 64 + tn * 4;
    float4 wb;
    wb.x = p.Wxb[g][jc+0] + p.Whb[g][jc+0];
    wb.y = p.Wxb[g][jc+1] + p.Whb[g][jc+1];
    wb.z = p.Wxb[g][jc+2] + p.Whb[g][jc+2];
    wb.w = p.Wxb[g][jc+3] + p.Whb[g][jc+3];
#pragma unroll
    for (int rr = 0; rr < 4; rr++) {
        int m = blockIdx.y * 64 + tm * 4 + rr;
        int b = m >> 9;
        int s = m & 511;
        float4 bg4 = *(const float4*)(p.bgate[g] + (size_t)b * HH + jc);
        float2 p0 = unpack2(acc2[rr][0]);
        float2 p1 = unpack2(acc2[rr][1]);
        float4 o;
        o.x = p0.x + wb.x + bg4.x;
        o.y = p0.y + wb.y + bg4.y;
        o.z = p1.x + wb.z + bg4.z;
        o.w = p1.y + wb.w + bg4.w;
        *(float4*)&g_XP[((size_t)s * BB + b) * NCOL + n0] = o;
    }
}

// ---------- persistent recurrent scan (FFMA2 inner product) ----------
// 128 CTAs: rb=blockIdx.x>>3 owns batch rows [rb*16,+16); cb=blockIdx.x&7 owns
// j in [cb*32,+32) across 4 gates. Weight slice (128KB) + cell state in SMEM.
__global__ __launch_bounds__(256, 1) void scan_kernel(ScanParams p) {
    extern __shared__ __align__(16) float smem_f[];
    float* Ws  = smem_f;                     // [k][cl] 256*128
    float* hs  = Ws + HH * CLS;              // [r][k]  16*256
    float* pre = hs + ROWS_PER_CTA * HH;     // [r][cl] 16*128
    float* cs  = pre + ROWS_PER_CTA * CLS;   // [r][jj] 16*32

    const int tid = threadIdx.x;
    const int cb = blockIdx.x & 7;
    const int rb = blockIdx.x >> 3;
    const int b0 = rb * ROWS_PER_CTA;
    const int j0 = cb * JS;

    for (int idx = tid; idx < CLS * HH; idx += 256) {
        int cl = idx >> 8;
        int k  = idx & 255;
        int g  = cl >> 5;
        int j  = j0 + (cl & 31);
        Ws[k * CLS + cl] = p.Wh[g][(size_t)j * HH + k];
    }
    for (int idx = tid; idx < ROWS_PER_CTA * JS; idx += 256) cs[idx] = 0.f;
    __syncthreads();

    const int cq = tid & 31;
    const int rp = tid >> 5;
    const int r0 = rp * 2;
    const int c0 = cq * 4;
    const int gg = c0 >> 5;
    const int n0 = gg * 256 + j0 + (c0 & 31);

    for (int t = 0; t < SS; t++) {
        const float* Hin = g_H[t & 1];
        for (int idx = tid * 4; idx < ROWS_PER_CTA * HH; idx += 1024) {
            int r = idx >> 8;
            int k = idx & 255;
            *(float4*)&hs[idx] = *(const float4*)&Hin[(size_t)(b0 + r) * HH + k];
        }

        // Prefetch this step's input-projection tile early (DRAM latency hide)
        const float* xp = g_XP + ((size_t)t * BB + b0) * NCOL;
        float4 x0 = *(const float4*)&xp[(size_t)r0 * NCOL + n0];
        float4 x1 = *(const float4*)&xp[(size_t)(r0 + 1) * NCOL + n0];
        __syncthreads();

        unsigned long long acc00 = 0ull, acc01 = 0ull, acc10 = 0ull, acc11 = 0ull;
        const float* hr0 = hs + r0 * HH;
        const float* hr1 = hr0 + HH;
        for (int kk = 0; kk < HH; kk += 4) {
            float4 h0v = *(const float4*)&hr0[kk];
            float4 h1v = *(const float4*)&hr1[kk];
            {
                ulonglong2 wp = *(const ulonglong2*)&Ws[(kk + 0) * CLS + c0];
                unsigned long long h0 = pack2(h0v.x, h0v.x);
                unsigned long long h1 = pack2(h1v.x, h1v.x);
                fma2(acc00, h0, wp.x); fma2(acc01, h0, wp.y);
                fma2(acc10, h1, wp.x); fma2(acc11, h1, wp.y);
            }
            {
                ulonglong2 wp = *(const ulonglong2*)&Ws[(kk + 1) * CLS + c0];
                unsigned long long h0 = pack2(h0v.y, h0v.y);
                unsigned long long h1 = pack2(h1v.y, h1v.y);
                fma2(acc00, h0, wp.x); fma2(acc01, h0, wp.y);
                fma2(acc10, h1, wp.x); fma2(acc11, h1, wp.y);
            }
            {
                ulonglong2 wp = *(const ulonglong2*)&Ws[(kk + 2) * CLS + c0];
                unsigned long long h0 = pack2(h0v.z, h0v.z);
                unsigned long long h1 = pack2(h1v.z, h1v.z);
                fma2(acc00, h0, wp.x); fma2(acc01, h0, wp.y);
                fma2(acc10, h1, wp.x); fma2(acc11, h1, wp.y);
            }
            {
                ulonglong2 wp = *(const ulonglong2*)&Ws[(kk + 3) * CLS + c0];
                unsigned long long h0 = pack2(h0v.w, h0v.w);
                unsigned long long h1 = pack2(h1v.w, h1v.w);
                fma2(acc00, h0, wp.x); fma2(acc01, h0, wp.y);
                fma2(acc10, h1, wp.x); fma2(acc11, h1, wp.y);
            }
        }

        float2 q00 = unpack2(acc00);
        float2 q01 = unpack2(acc01);
        float2 q10 = unpack2(acc10);
        float2 q11 = unpack2(acc11);
        *(float4*)&pre[r0 * CLS + c0] =
            make_float4(q00.x + x0.x, q00.y + x0.y, q01.x + x0.z, q01.y + x0.w);
        *(float4*)&pre[(r0 + 1) * CLS + c0] =
            make_float4(q10.x + x1.x, q10.y + x1.y, q11.x + x1.z, q11.y + x1.w);
        __syncthreads();

        float* Hout = g_H[(t + 1) & 1];
#pragma unroll
        for (int u = 0; u < 2; u++) {
            int idx = tid * 2 + u;
            int r  = idx >> 5;
            int jj = idx & 31;
            float pg = pre[r * CLS + jj];
            float pi = pre[r * CLS + 32 + jj];
            float pf = pre[r * CLS + 64 + jj];
            float po = pre[r * CLS + 96 + jj];
            float gv = tanhf(pg);
            float iv = 1.f / (1.f + expf(-pi));
            float fv = 1.f / (1.f + expf(-pf));
            float ov = 1.f / (1.f + expf(-po));
            float cv = fmaf(gv, iv, cs[r * JS + jj] * fv);
            cs[r * JS + jj] = cv;
            Hout[(size_t)(b0 + r) * HH + (j0 + jj)] = tanhf(cv) * ov;
        }
        __threadfence();
        __syncthreads();

        if (tid == 0) {
            unsigned arrived = atomicAdd(&g_barCnt[rb], 1u);
            if (arrived == 7u) {
                g_barCnt[rb] = 0u;
                __threadfence();
                atomicExch(&g_barGen[rb], (unsigned)(t + 1));
            } else {
                while (*(volatile unsigned*)&g_barGen[rb] < (unsigned)(t + 1)) { }
            }
            __threadfence();
        }
        __syncthreads();
    }
}

// ---------- final projection + softmax ----------
__global__ __launch_bounds__(128) void proj_softmax(const float* __restrict__ Wph,
                                                    const float* __restrict__ Wphb,
                                                    const float* __restrict__ bp,
                                                    float* __restrict__ out) {
    __shared__ float hsh[HH];
    __shared__ float red[OO];
    const int b = blockIdx.x;
    const int o = threadIdx.x;
    const float* Hfin = g_H[0];           // after t=511, buffer (512 & 1) == 0
    hsh[o]       = Hfin[(size_t)b * HH + o];
    hsh[o + 128] = Hfin[(size_t)b * HH + o + 128];
    __syncthreads();

    float acc = 0.f;
    const float* wr = Wph + (size_t)o * HH;
#pragma unroll 8
    for (int k = 0; k < HH; k += 4) {
        float4 w = *(const float4*)&wr[k];
        acc = fmaf(hsh[k],   w.x, acc);
        acc = fmaf(hsh[k+1], w.y, acc);
        acc = fmaf(hsh[k+2], w.z, acc);
        acc = fmaf(hsh[k+3], w.w, acc);
    }
    float pv = acc + Wphb[o] + bp[(size_t)b * OO + o];

    red[o] = pv;
    __syncthreads();
#pragma unroll
    for (int s = 64; s > 0; s >>= 1) {
        if (o < s) red[o] = fmaxf(red[o], red[o + s]);
        __syncthreads();
    }
    float mx = red[0];
    __syncthreads();
    float e = expf(pv - mx);
    red[o] = e;
    __syncthreads();
#pragma unroll
    for (int s = 64; s > 0; s >>= 1) {
        if (o < s) red[o] += red[o + s];
        __syncthreads();
    }
    out[(size_t)b * OO + o] = e / red[0];
}

// ---------- launch ----------
extern "C" void kernel_launch(void* const* d_in, const int* in_sizes, int n_in,
                              void* d_out, int out_size) {
    (void)in_sizes; (void)n_in; (void)out_size;
    const float* x     = (const float*)d_in[0];
    const float* Wgx_w = (const float*)d_in[1];  const float* Wgx_b = (const float*)d_in[2];
    const float* Wgh_w = (const float*)d_in[3];  const float* Wgh_b = (const float*)d_in[4];
    const float* Wix_w = (const float*)d_in[5];  const float* Wix_b = (const float*)d_in[6];
    const float* Wih_w = (const float*)d_in[7];  const float* Wih_b = (const float*)d_in[8];
    const float* Wfx_w = (const float*)d_in[9];  const float* Wfx_b = (const float*)d_in[10];
    const float* Wfh_w = (const float*)d_in[11]; const float* Wfh_b = (const float*)d_in[12];
    const float* Wox_w = (const float*)d_in[13]; const float* Wox_b = (const float*)d_in[14];
    const float* Woh_w = (const float*)d_in[15]; const float* Woh_b = (const float*)d_in[16];
    const float* Wph_w = (const float*)d_in[17]; const float* Wph_b = (const float*)d_in[18];
    const float* bg    = (const float*)d_in[19];
    const float* bi    = (const float*)d_in[20];
    const float* bf    = (const float*)d_in[21];
    const float* bo    = (const float*)d_in[22];
    const float* bp    = (const float*)d_in[23];
    float* out = (float*)d_out;

    static bool attr_done = false;
    if (!attr_done) {
        cudaFuncSetAttribute(scan_kernel, cudaFuncAttributeMaxDynamicSharedMemorySize, SCAN_SMEM);
        attr_done = true;
    }

    P1Params p1;
    p1.x = x;
    p1.Wx[0] = Wgx_w; p1.Wx[1] = Wix_w; p1.Wx[2] = Wfx_w; p1.Wx[3] = Wox_w;
    p1.Wxb[0] = Wgx_b; p1.Wxb[1] = Wix_b; p1.Wxb[2] = Wfx_b; p1.Wxb[3] = Wox_b;
    p1.Whb[0] = Wgh_b; p1.Whb[1] = Wih_b; p1.Whb[2] = Wfh_b; p1.Whb[3] = Woh_b;
    p1.bgate[0] = bg; p1.bgate[1] = bi; p1.bgate[2] = bf; p1.bgate[3] = bo;

    ScanParams sp;
    sp.Wh[0] = Wgh_w; sp.Wh[1] = Wih_w; sp.Wh[2] = Wfh_w; sp.Wh[3] = Woh_w;

    init_kernel<<<(2 * BB * HH + 255) / 256, 256>>>();
    dim3 g1(NCOL / 64, (BB * SS) / 64);
    p1_gemm<<<g1, 256>>>(p1);
    scan_kernel<<<128, 256, SCAN_SMEM>>>(sp);
    proj_softmax<<<BB, OO>>>(Wph_w, Wph_b, bp, out);
}

// round 8
// speedup vs baseline: 2.1012x; 1.2598x over previous
#include <cuda_runtime.h>
#include <math.h>

#define BB 256
#define SS 512
#define DD 256
#define HH 256
#define OO 128
#define NCOL 1024            // 4 gates * HH
#define ROWS_PER_CTA 16
#define JS 32                // hidden-j slice per scan CTA
#define CLS 128              // 4 gates * JS (interleaved [k][jj*4+g])
#define NGROUPS 16
// Ws + hs (floats) + exchange buffer (1024 ull)
#define SCAN_SMEM ((HH*CLS + ROWS_PER_CTA*HH) * 4 + 1024 * 8)

// ---------- device scratch (static; no runtime allocation) ----------
__device__ float g_XP[(size_t)SS * BB * NCOL];   // [s][b][n], n = gate*256 + j
__device__ float g_H[2][BB * HH];
__device__ unsigned g_barCnt[NGROUPS];
__device__ unsigned g_barGen[NGROUPS];

struct P1Params {
    const float* x;
    const float* Wx[4];
    const float* Wxb[4];
    const float* Whb[4];
    const float* bgate[4];
};
struct ScanParams { const float* Wh[4]; };

// ---------- packed f32x2 helpers (Blackwell FFMA2) ----------
__device__ __forceinline__ unsigned long long pack2(float lo, float hi) {
    unsigned long long r;
    asm("mov.b64 %0, {%1, %2};"
        : "=l"(r) : "r"(__float_as_uint(lo)), "r"(__float_as_uint(hi)));
    return r;
}
__device__ __forceinline__ void fma2(unsigned long long& d,
                                     unsigned long long a, unsigned long long b) {
    asm("fma.rn.f32x2 %0, %1, %2, %0;" : "+l"(d) : "l"(a), "l"(b));
}
__device__ __forceinline__ void add2(unsigned long long& d, unsigned long long a) {
    asm("add.rn.f32x2 %0, %0, %1;" : "+l"(d) : "l"(a));
}
__device__ __forceinline__ float2 unpack2(unsigned long long v) {
    unsigned lo, hi;
    asm("mov.b64 {%0, %1}, %2;" : "=r"(lo), "=r"(hi) : "l"(v));
    return make_float2(__uint_as_float(lo), __uint_as_float(hi));
}

// ---------- init: zero state + barriers ----------
__global__ __launch_bounds__(256) void init_kernel() {
    unsigned i = blockIdx.x * blockDim.x + threadIdx.x;
    if (i < 2u * BB * HH) ((float*)g_H)[i] = 0.f;
    if (i < NGROUPS) { g_barCnt[i] = 0u; g_barGen[i] = 0u; }
}

// ---------- phase 1: XP = x @ Wx^T + (Wx_b + Wh_b) + bgate ----------
// M=131072, N=1024, K=256. 128x128 tile, 256 thr, 8x8 per thread (FFMA2).
__global__ __launch_bounds__(256, 2) void p1_gemm(P1Params p) {
    __shared__ __align__(16) float As[16][132];
    __shared__ __align__(16) float Bs[16][132];
    const int tid = threadIdx.x;
    const int tm = tid >> 4, tn = tid & 15;
    const int ml = tid >> 2;               // 0..63 (rows ml and ml+64)
    const int kl = (tid & 3) * 4;          // 0,4,8,12
    const int g   = blockIdx.x >> 1;
    const int j0g = (blockIdx.x & 1) * 128;

    const float* Aptr0 = p.x + (size_t)(blockIdx.y * 128 + ml) * DD + kl;
    const float* Aptr1 = Aptr0 + (size_t)64 * DD;
    const float* Bptr0 = p.Wx[g] + (size_t)(j0g + ml) * DD + kl;
    const float* Bptr1 = Bptr0 + (size_t)64 * DD;

    unsigned long long acc[8][4];
#pragma unroll
    for (int r = 0; r < 8; r++)
#pragma unroll
        for (int c = 0; c < 4; c++) acc[r][c] = 0ull;

    for (int kt = 0; kt < DD; kt += 16) {
        float4 a0 = *(const float4*)(Aptr0 + kt);
        float4 a1 = *(const float4*)(Aptr1 + kt);
        float4 b0 = *(const float4*)(Bptr0 + kt);
        float4 b1 = *(const float4*)(Bptr1 + kt);
        As[kl+0][ml] = a0.x; As[kl+1][ml] = a0.y; As[kl+2][ml] = a0.z; As[kl+3][ml] = a0.w;
        As[kl+0][ml+64] = a1.x; As[kl+1][ml+64] = a1.y; As[kl+2][ml+64] = a1.z; As[kl+3][ml+64] = a1.w;
        Bs[kl+0][ml] = b0.x; Bs[kl+1][ml] = b0.y; Bs[kl+2][ml] = b0.z; Bs[kl+3][ml] = b0.w;
        Bs[kl+0][ml+64] = b1.x; Bs[kl+1][ml+64] = b1.y; Bs[kl+2][ml+64] = b1.z; Bs[kl+3][ml+64] = b1.w;
        __syncthreads();
#pragma unroll
        for (int kk = 0; kk < 16; kk++) {
            float4 av0 = *(const float4*)&As[kk][tm * 8];
            float4 av1 = *(const float4*)&As[kk][tm * 8 + 4];
            ulonglong2 bv0 = *(const ulonglong2*)&Bs[kk][tn * 8];
            ulonglong2 bv1 = *(const ulonglong2*)&Bs[kk][tn * 8 + 4];
            float ar[8] = {av0.x, av0.y, av0.z, av0.w, av1.x, av1.y, av1.z, av1.w};
#pragma unroll
            for (int r = 0; r < 8; r++) {
                unsigned long long ap = pack2(ar[r], ar[r]);
                fma2(acc[r][0], ap, bv0.x);
                fma2(acc[r][1], ap, bv0.y);
                fma2(acc[r][2], ap, bv1.x);
                fma2(acc[r][3], ap, bv1.y);
            }
        }
        __syncthreads();
    }

    const int jc = j0g + tn * 8;                 // col-in-gate base
    const int n0 = blockIdx.x * 128 + tn * 8;    // global col base
    float4 wbl = *(const float4*)&p.Wxb[g][jc];
    float4 wbh = *(const float4*)&p.Wxb[g][jc + 4];
    float4 hbl = *(const float4*)&p.Whb[g][jc];
    float4 hbh = *(const float4*)&p.Whb[g][jc + 4];
    wbl.x += hbl.x; wbl.y += hbl.y; wbl.z += hbl.z; wbl.w += hbl.w;
    wbh.x += hbh.x; wbh.y += hbh.y; wbh.z += hbh.z; wbh.w += hbh.w;
#pragma unroll
    for (int rr = 0; rr < 8; rr++) {
        int m = blockIdx.y * 128 + tm * 8 + rr;
        int b = m >> 9;
        int s = m & 511;
        float4 bgl = *(const float4*)(p.bgate[g] + (size_t)b * HH + jc);
        float4 bgh = *(const float4*)(p.bgate[g] + (size_t)b * HH + jc + 4);
        float2 p0 = unpack2(acc[rr][0]);
        float2 p1 = unpack2(acc[rr][1]);
        float2 p2 = unpack2(acc[rr][2]);
        float2 p3 = unpack2(acc[rr][3]);
        float4 o0 = make_float4(p0.x + wbl.x + bgl.x, p0.y + wbl.y + bgl.y,
                                p1.x + wbl.z + bgl.z, p1.y + wbl.w + bgl.w);
        float4 o1 = make_float4(p2.x + wbh.x + bgh.x, p2.y + wbh.y + bgh.y,
                                p3.x + wbh.z + bgh.z, p3.y + wbh.w + bgh.w);
        float* dst = &g_XP[((size_t)s * BB + b) * NCOL + n0];
        *(float4*)dst = o0;
        *(float4*)(dst + 4) = o1;
    }
}

// ---------- persistent recurrent scan ----------
// 128 CTAs: rb owns batch rows [rb*16,+16); cb owns j in [cb*32,+32).
// Ws interleaved [k][jj*4+g] resident in SMEM. Thread (kh,rg,jj): 4 rows x
// 1 jj x 4 gates over half of k; k-halves merged via 8KB smem exchange.
// Gate math in-register; cell state in registers.
__global__ __launch_bounds__(256, 1) void scan_kernel(ScanParams p) {
    extern __shared__ __align__(16) float smem_f[];
    float* Ws = smem_f;                              // [k][c] 256*128
    float* hs = Ws + HH * CLS;                       // [r][k] 16*256
    unsigned long long* ex = (unsigned long long*)(hs + ROWS_PER_CTA * HH); // [2][4][4][32]

    const int tid = threadIdx.x;
    const int cb = blockIdx.x & 7;
    const int rb = blockIdx.x >> 3;
    const int b0 = rb * ROWS_PER_CTA;
    const int j0 = cb * JS;

    // Ws load, gate-interleaved: Ws[k*128 + jj*4 + g] = Wh_g[j0+jj][k]
    for (int idx = tid; idx < CLS * HH; idx += 256) {
        int k = idx >> 7;
        int c = idx & 127;
        int jjx = c >> 2;
        int gx = c & 3;
        Ws[k * CLS + c] = p.Wh[gx][(size_t)(j0 + jjx) * HH + k];
    }
    __syncthreads();

    const int kh = tid >> 7;            // k-half
    const int rg = (tid >> 5) & 3;      // row group (4 rows)
    const int jj = tid & 31;
    const int rbase = rg * 4;
    const int kbase = kh * 128;
    const int rown0 = rbase + 2 * kh;   // owned rows: rown0, rown0+1
    float c0v = 0.f, c1v = 0.f;         // cell state (registers)

    unsigned long long* exw = ex + (size_t)((kh * 4 + rg) * 4) * 32 + jj;
    unsigned long long* exr = ex + (size_t)(((1 - kh) * 4 + rg) * 4) * 32 + jj;

    const float* wrow = Ws + (size_t)kbase * CLS + jj * 4;

    for (int t = 0; t < SS; t++) {
        const float* Hin = g_H[t & 1];
        for (int idx = tid * 4; idx < ROWS_PER_CTA * HH; idx += 1024) {
            *(float4*)&hs[idx] =
                *(const float4*)&Hin[(size_t)(b0 + (idx >> 8)) * HH + (idx & 255)];
        }
        // prefetch this step's xp for the two owned rows (4 gates each)
        const float* xpb = g_XP + ((size_t)t * BB + b0) * NCOL + j0 + jj;
        const float* xpr0 = xpb + (size_t)rown0 * NCOL;
        const float* xpr1 = xpr0 + NCOL;
        float xg0 = xpr0[0], xi0 = xpr0[256], xf0 = xpr0[512], xo0 = xpr0[768];
        float xg1 = xpr1[0], xi1 = xpr1[256], xf1 = xpr1[512], xo1 = xpr1[768];
        __syncthreads();

        unsigned long long aGI0 = 0, aGI1 = 0, aGI2 = 0, aGI3 = 0;
        unsigned long long aFO0 = 0, aFO1 = 0, aFO2 = 0, aFO3 = 0;
        const float* h0 = hs + (rbase + 0) * HH + kbase;
        const float* h1 = h0 + HH;
        const float* h2 = h1 + HH;
        const float* h3 = h2 + HH;
        for (int k4 = 0; k4 < 128; k4 += 4) {
            float4 v0 = *(const float4*)&h0[k4];
            float4 v1 = *(const float4*)&h1[k4];
            float4 v2 = *(const float4*)&h2[k4];
            float4 v3 = *(const float4*)&h3[k4];
            {
                ulonglong2 wp = *(const ulonglong2*)&wrow[(size_t)(k4 + 0) * CLS];
                unsigned long long p0 = pack2(v0.x, v0.x), p1 = pack2(v1.x, v1.x);
                unsigned long long p2 = pack2(v2.x, v2.x), p3 = pack2(v3.x, v3.x);
                fma2(aGI0, p0, wp.x); fma2(aFO0, p0, wp.y);
                fma2(aGI1, p1, wp.x); fma2(aFO1, p1, wp.y);
                fma2(aGI2, p2, wp.x); fma2(aFO2, p2, wp.y);
                fma2(aGI3, p3, wp.x); fma2(aFO3, p3, wp.y);
            }
            {
                ulonglong2 wp = *(const ulonglong2*)&wrow[(size_t)(k4 + 1) * CLS];
                unsigned long long p0 = pack2(v0.y, v0.y), p1 = pack2(v1.y, v1.y);
                unsigned long long p2 = pack2(v2.y, v2.y), p3 = pack2(v3.y, v3.y);
                fma2(aGI0, p0, wp.x); fma2(aFO0, p0, wp.y);
                fma2(aGI1, p1, wp.x); fma2(aFO1, p1, wp.y);
                fma2(aGI2, p2, wp.x); fma2(aFO2, p2, wp.y);
                fma2(aGI3, p3, wp.x); fma2(aFO3, p3, wp.y);
            }
            {
                ulonglong2 wp = *(const ulonglong2*)&wrow[(size_t)(k4 + 2) * CLS];
                unsigned long long p0 = pack2(v0.z, v0.z), p1 = pack2(v1.z, v1.z);
                unsigned long long p2 = pack2(v2.z, v2.z), p3 = pack2(v3.z, v3.z);
                fma2(aGI0, p0, wp.x); fma2(aFO0, p0, wp.y);
                fma2(aGI1, p1, wp.x); fma2(aFO1, p1, wp.y);
                fma2(aGI2, p2, wp.x); fma2(aFO2, p2, wp.y);
                fma2(aGI3, p3, wp.x); fma2(aFO3, p3, wp.y);
            }
            {
                ulonglong2 wp = *(const ulonglong2*)&wrow[(size_t)(k4 + 3) * CLS];
                unsigned long long p0 = pack2(v0.w, v0.w), p1 = pack2(v1.w, v1.w);
                unsigned long long p2 = pack2(v2.w, v2.w), p3 = pack2(v3.w, v3.w);
                fma2(aGI0, p0, wp.x); fma2(aFO0, p0, wp.y);
                fma2(aGI1, p1, wp.x); fma2(aFO1, p1, wp.y);
                fma2(aGI2, p2, wp.x); fma2(aFO2, p2, wp.y);
                fma2(aGI3, p3, wp.x); fma2(aFO3, p3, wp.y);
            }
        }

        // exchange: write partials for NON-owned rows, read peer's for owned rows
        unsigned long long wA = kh ? aGI0 : aGI2;
        unsigned long long wB = kh ? aFO0 : aFO2;
        unsigned long long wC = kh ? aGI1 : aGI3;
        unsigned long long wD = kh ? aFO1 : aFO3;
        unsigned long long oGI0 = kh ? aGI2 : aGI0;
        unsigned long long oFO0 = kh ? aFO2 : aFO0;
        unsigned long long oGI1 = kh ? aGI3 : aGI1;
        unsigned long long oFO1 = kh ? aFO3 : aFO1;
        exw[0] = wA; exw[32] = wB; exw[64] = wC; exw[96] = wD;
        __syncthreads();
        add2(oGI0, exr[0]);
        add2(oFO0, exr[32]);
        add2(oGI1, exr[64]);
        add2(oFO1, exr[96]);

        // gate math fully in-register for the 2 owned rows
        float* Hout = g_H[(t + 1) & 1];
        {
            float2 gi = unpack2(oGI0);
            float2 fo = unpack2(oFO0);
            float pg = gi.x + xg0, pi = gi.y + xi0, pf = fo.x + xf0, po = fo.y + xo0;
            float gv = tanhf(pg);
            float iv = 1.f / (1.f + expf(-pi));
            float fv = 1.f / (1.f + expf(-pf));
            float ov = 1.f / (1.f + expf(-po));
            c0v = fmaf(gv, iv, c0v * fv);
            Hout[(size_t)(b0 + rown0) * HH + (j0 + jj)] = tanhf(c0v) * ov;
        }
        {
            float2 gi = unpack2(oGI1);
            float2 fo = unpack2(oFO1);
            float pg = gi.x + xg1, pi = gi.y + xi1, pf = fo.x + xf1, po = fo.y + xo1;
            float gv = tanhf(pg);
            float iv = 1.f / (1.f + expf(-pi));
            float fv = 1.f / (1.f + expf(-pf));
            float ov = 1.f / (1.f + expf(-po));
            c1v = fmaf(gv, iv, c1v * fv);
            Hout[(size_t)(b0 + rown0 + 1) * HH + (j0 + jj)] = tanhf(c1v) * ov;
        }
        __threadfence();
        __syncthreads();

        if (tid == 0) {
            unsigned arrived = atomicAdd(&g_barCnt[rb], 1u);
            if (arrived == 7u) {
                g_barCnt[rb] = 0u;
                __threadfence();
                atomicExch(&g_barGen[rb], (unsigned)(t + 1));
            } else {
                while (*(volatile unsigned*)&g_barGen[rb] < (unsigned)(t + 1)) { }
            }
            __threadfence();
        }
        __syncthreads();
    }
}

// ---------- final projection + softmax ----------
__global__ __launch_bounds__(128) void proj_softmax(const float* __restrict__ Wph,
                                                    const float* __restrict__ Wphb,
                                                    const float* __restrict__ bp,
                                                    float* __restrict__ out) {
    __shared__ float hsh[HH];
    __shared__ float red[OO];
    const int b = blockIdx.x;
    const int o = threadIdx.x;
    const float* Hfin = g_H[0];           // after t=511, buffer (512 & 1) == 0
    hsh[o]       = Hfin[(size_t)b * HH + o];
    hsh[o + 128] = Hfin[(size_t)b * HH + o + 128];
    __syncthreads();

    float acc = 0.f;
    const float* wr = Wph + (size_t)o * HH;
#pragma unroll 8
    for (int k = 0; k < HH; k += 4) {
        float4 w = *(const float4*)&wr[k];
        acc = fmaf(hsh[k],   w.x, acc);
        acc = fmaf(hsh[k+1], w.y, acc);
        acc = fmaf(hsh[k+2], w.z, acc);
        acc = fmaf(hsh[k+3], w.w, acc);
    }
    float pv = acc + Wphb[o] + bp[(size_t)b * OO + o];

    red[o] = pv;
    __syncthreads();
#pragma unroll
    for (int s = 64; s > 0; s >>= 1) {
        if (o < s) red[o] = fmaxf(red[o], red[o + s]);
        __syncthreads();
    }
    float mx = red[0];
    __syncthreads();
    float e = expf(pv - mx);
    red[o] = e;
    __syncthreads();
#pragma unroll
    for (int s = 64; s > 0; s >>= 1) {
        if (o < s) red[o] += red[o + s];
        __syncthreads();
    }
    out[(size_t)b * OO + o] = e / red[0];
}

// ---------- launch ----------
extern "C" void kernel_launch(void* const* d_in, const int* in_sizes, int n_in,
                              void* d_out, int out_size) {
    (void)in_sizes; (void)n_in; (void)out_size;
    const float* x     = (const float*)d_in[0];
    const float* Wgx_w = (const float*)d_in[1];  const float* Wgx_b = (const float*)d_in[2];
    const float* Wgh_w = (const float*)d_in[3];  const float* Wgh_b = (const float*)d_in[4];
    const float* Wix_w = (const float*)d_in[5];  const float* Wix_b = (const float*)d_in[6];
    const float* Wih_w = (const float*)d_in[7];  const float* Wih_b = (const float*)d_in[8];
    const float* Wfx_w = (const float*)d_in[9];  const float* Wfx_b = (const float*)d_in[10];
    const float* Wfh_w = (const float*)d_in[11]; const float* Wfh_b = (const float*)d_in[12];
    const float* Wox_w = (const float*)d_in[13]; const float* Wox_b = (const float*)d_in[14];
    const float* Woh_w = (const float*)d_in[15]; const float* Woh_b = (const float*)d_in[16];
    const float* Wph_w = (const float*)d_in[17]; const float* Wph_b = (const float*)d_in[18];
    const float* bg    = (const float*)d_in[19];
    const float* bi    = (const float*)d_in[20];
    const float* bf    = (const float*)d_in[21];
    const float* bo    = (const float*)d_in[22];
    const float* bp    = (const float*)d_in[23];
    float* out = (float*)d_out;

    static bool attr_done = false;
    if (!attr_done) {
        cudaFuncSetAttribute(scan_kernel, cudaFuncAttributeMaxDynamicSharedMemorySize, SCAN_SMEM);
        attr_done = true;
    }

    P1Params p1;
    p1.x = x;
    p1.Wx[0] = Wgx_w; p1.Wx[1] = Wix_w; p1.Wx[2] = Wfx_w; p1.Wx[3] = Wox_w;
    p1.Wxb[0] = Wgx_b; p1.Wxb[1] = Wix_b; p1.Wxb[2] = Wfx_b; p1.Wxb[3] = Wox_b;
    p1.Whb[0] = Wgh_b; p1.Whb[1] = Wih_b; p1.Whb[2] = Wfh_b; p1.Whb[3] = Woh_b;
    p1.bgate[0] = bg; p1.bgate[1] = bi; p1.bgate[2] = bf; p1.bgate[3] = bo;

    ScanParams sp;
    sp.Wh[0] = Wgh_w; sp.Wh[1] = Wih_w; sp.Wh[2] = Wfh_w; sp.Wh[3] = Woh_w;

    init_kernel<<<(2 * BB * HH + 255) / 256, 256>>>();
    dim3 g1(NCOL / 128, (BB * SS) / 128);
    p1_gemm<<<g1, 256>>>(p1);
    scan_kernel<<<128, 256, SCAN_SMEM>>>(sp);
    proj_softmax<<<BB, OO>>>(Wph_w, Wph_b, bp, out);
}